// round 4
// baseline (speedup 1.0000x reference)
#include <cuda_runtime.h>
#include <cuda_fp16.h>
#include <cstdint>
#include <cstddef>

#define D_MODEL 2048
#define D_FF    8192
#define M_TOK   16384   // 4 * 4096 tokens

// ---------------- device scratch (static; no allocations allowed) ----------------
__device__ __half g_w1q[(size_t)D_FF * D_MODEL];    // 32 MB  ternarized fc1 weights (fp16)
__device__ __half g_w2q[(size_t)D_MODEL * D_FF];    // 32 MB  ternarized fc2 weights (fp16)
__device__ __half g_x  [(size_t)M_TOK * D_MODEL];   // 64 MB  x in fp16
__device__ __half g_h  [(size_t)M_TOK * D_FF];      // 256 MB intermediate activations (fp16)
__device__ double g_part[2][1024];                  // abs-sum partials (deterministic reduce)
__device__ float  g_scale[2];                       // absmean scales

// ---------------- deterministic absmean reduction (fp64, fixed tree order) ----------------
__global__ void abssum_partial(const float* __restrict__ w, int n, int sidx) {
    __shared__ double sd[256];
    double s = 0.0;
    for (int i = blockIdx.x * 256 + threadIdx.x; i < n; i += 1024 * 256)
        s += (double)fabsf(w[i]);
    sd[threadIdx.x] = s;
    __syncthreads();
    for (int o = 128; o > 0; o >>= 1) {
        if (threadIdx.x < o) sd[threadIdx.x] += sd[threadIdx.x + o];
        __syncthreads();
    }
    if (threadIdx.x == 0) g_part[sidx][blockIdx.x] = sd[0];
}

__global__ void finalize_scale(int sidx, double inv_n) {
    __shared__ double sd[256];
    int t = threadIdx.x;
    double s = g_part[sidx][t] + g_part[sidx][t + 256]
             + g_part[sidx][t + 512] + g_part[sidx][t + 768];
    sd[t] = s;
    __syncthreads();
    for (int o = 128; o > 0; o >>= 1) {
        if (t < o) sd[t] += sd[t + o];
        __syncthreads();
    }
    if (t == 0) g_scale[sidx] = (float)(sd[0] * inv_n);
}

// ---------------- ternarize weights to fp16 {-1,0,+1} ----------------
__device__ __forceinline__ float tern(float v, float t) {
    return (fabsf(v) >= t) ? (v > 0.0f ? 1.0f : -1.0f) : 0.0f;
}

__global__ void ternarize4(const float4* __restrict__ w, __half* __restrict__ wq,
                           int n4, int sidx) {
    const float t = 0.7f * g_scale[sidx];
    int i = blockIdx.x * blockDim.x + threadIdx.x;
    if (i < n4) {
        float4 v = w[i];
        __half2 lo = __floats2half2_rn(tern(v.x, t), tern(v.y, t));
        __half2 hi = __floats2half2_rn(tern(v.z, t), tern(v.w, t));
        *(__half2*)(wq + (size_t)i * 4)     = lo;
        *(__half2*)(wq + (size_t)i * 4 + 2) = hi;
    }
}

// ---------------- x: fp32 -> fp16 ----------------
__global__ void convert4(const float4* __restrict__ x, __half* __restrict__ xh, int n4) {
    int i = blockIdx.x * blockDim.x + threadIdx.x;
    if (i < n4) {
        float4 v = x[i];
        *(__half2*)(xh + (size_t)i * 4)     = __floats2half2_rn(v.x, v.y);
        *(__half2*)(xh + (size_t)i * 4 + 2) = __floats2half2_rn(v.z, v.w);
    }
}

// ---------------- epilogue helpers ----------------
__device__ __forceinline__ float gelu_exact(float v) {
    return 0.5f * v * (1.0f + erff(v * 0.70710678118654752440f));
}
__device__ __forceinline__ void store2(__half* C, size_t off, float v0, float v1) {
    *(__half2*)(C + off) = __floats2half2_rn(v0, v1);
}
__device__ __forceinline__ void store2(float* C, size_t off, float v0, float v1) {
    *(float2*)(C + off) = make_float2(v0, v1);
}

__device__ __forceinline__ void cp_async16(uint32_t smem_dst, const void* gmem_src) {
    asm volatile("cp.async.cg.shared.global [%0], [%1], 16;\n"
                 :: "r"(smem_dst), "l"(gmem_src));
}

// ---------------- GEMM: C[M,N] = A[M,K] * B[N,K]^T + bias (opt. GELU) ----------------
// 128x128x32 CTA tile, 256 threads, 8 warps in 4(M) x 2(N), warp tile 32x64,
// mma.sync.m16n8k16 fp16->fp32, 3-stage cp.async pipeline (dynamic smem).
// Per-stage smem: A 128x40 halves + B 128x40 halves = 20480 B; 3 stages = 61440 B.
#define STAGES      3
#define STAGE_HALF  10240               // halves per stage (A + B)
#define LDA_S       40                  // row pitch in halves (BK=32 + 8 pad)
#define SMEM_BYTES  (STAGES * STAGE_HALF * 2)

template <bool GELU, typename OutT>
__global__ void __launch_bounds__(256)
gemm_hmma(const __half* __restrict__ A, const __half* __restrict__ B,
          const float* __restrict__ bias, OutT* __restrict__ C,
          int Mdim, int Ndim, int Kdim) {
    constexpr int BM = 128, BN = 128, BK = 32;
    extern __shared__ __half sh[];
    const uint32_t sh_base = (uint32_t)__cvta_generic_to_shared(sh);

    const int tid  = threadIdx.x;
    const int bm   = blockIdx.y * BM, bn = blockIdx.x * BN;
    const int lrow = tid >> 2, lcol = (tid & 3) * 8;
    const __half* gA = A + (size_t)(bm + lrow) * Kdim + lcol;
    const __half* gB = B + (size_t)(bn + lrow) * Kdim + lcol;

    const int warp = tid >> 5, lane = tid & 31;
    const int wm = (warp & 3) * 32, wn = (warp >> 2) * 64;
    const int g = lane >> 2, q = lane & 3;

    // smem addresses this thread writes (A row lrow / lrow+64, B row lrow / lrow+64)
    const uint32_t sA0 = sh_base + (uint32_t)(lrow * LDA_S + lcol) * 2;
    const uint32_t sA1 = sA0 + 64 * LDA_S * 2;
    const uint32_t sB0 = sA0 + STAGE_HALF;          // B block offset = 5120 halves * 2 B
    const uint32_t sB1 = sB0 + 64 * LDA_S * 2;

    auto load_stage = [&](int ks, int s) {
        const size_t ko = (size_t)ks * BK;
        const uint32_t so = (uint32_t)(s * STAGE_HALF * 2);
        cp_async16(sA0 + so, gA + ko);
        cp_async16(sA1 + so, gA + (size_t)64 * Kdim + ko);
        cp_async16(sB0 + so, gB + ko);
        cp_async16(sB1 + so, gB + (size_t)64 * Kdim + ko);
    };

    float acc[2][8][4];
#pragma unroll
    for (int a = 0; a < 2; a++)
#pragma unroll
        for (int b = 0; b < 8; b++)
#pragma unroll
            for (int c = 0; c < 4; c++) acc[a][b][c] = 0.0f;

    const int NS = Kdim / BK;
    load_stage(0, 0);
    asm volatile("cp.async.commit_group;\n");
    load_stage(1, 1);
    asm volatile("cp.async.commit_group;\n");
    asm volatile("cp.async.wait_group 1;\n");
    __syncthreads();

    int s = 0;
    for (int ks = 0; ks < NS; ks++) {
        const __half* As = sh + s * STAGE_HALF;
        const __half* Bs = sh + s * STAGE_HALF + 5120;

#pragma unroll
        for (int kk = 0; kk < 2; kk++) {
            const int k0 = kk * 16 + q * 2;
            uint32_t af[2][4];
#pragma unroll
            for (int im = 0; im < 2; im++) {
                const int r = wm + im * 16 + g;
                af[im][0] = *(const uint32_t*)&As[r * LDA_S + k0];
                af[im][1] = *(const uint32_t*)&As[(r + 8) * LDA_S + k0];
                af[im][2] = *(const uint32_t*)&As[r * LDA_S + k0 + 8];
                af[im][3] = *(const uint32_t*)&As[(r + 8) * LDA_S + k0 + 8];
            }
            uint32_t bf[8][2];
#pragma unroll
            for (int in_ = 0; in_ < 8; in_++) {
                const int r = wn + in_ * 8 + g;
                bf[in_][0] = *(const uint32_t*)&Bs[r * LDA_S + k0];
                bf[in_][1] = *(const uint32_t*)&Bs[r * LDA_S + k0 + 8];
            }
#pragma unroll
            for (int im = 0; im < 2; im++)
#pragma unroll
                for (int in_ = 0; in_ < 8; in_++) {
                    float* d = acc[im][in_];
                    asm volatile(
                        "mma.sync.aligned.m16n8k16.row.col.f32.f16.f16.f32 "
                        "{%0,%1,%2,%3},{%4,%5,%6,%7},{%8,%9},{%0,%1,%2,%3};\n"
                        : "+f"(d[0]), "+f"(d[1]), "+f"(d[2]), "+f"(d[3])
                        : "r"(af[im][0]), "r"(af[im][1]), "r"(af[im][2]), "r"(af[im][3]),
                          "r"(bf[in_][0]), "r"(bf[in_][1]));
                }
        }

        if (ks + 2 < NS) {
            int sn = s + 2; if (sn >= STAGES) sn -= STAGES;
            load_stage(ks + 2, sn);
        }
        asm volatile("cp.async.commit_group;\n");
        asm volatile("cp.async.wait_group 1;\n");
        __syncthreads();
        if (++s == STAGES) s = 0;
    }

    // epilogue: bias (+ optional exact GELU), vectorized pair stores
#pragma unroll
    for (int im = 0; im < 2; im++) {
#pragma unroll
        for (int in_ = 0; in_ < 8; in_++) {
            const int m0 = bm + wm + im * 16 + g;
            const int n0 = bn + wn + in_ * 8 + q * 2;
            const float bia0 = bias[n0], bia1 = bias[n0 + 1];
            float v0 = acc[im][in_][0] + bia0;
            float v1 = acc[im][in_][1] + bia1;
            float v2 = acc[im][in_][2] + bia0;
            float v3 = acc[im][in_][3] + bia1;
            if (GELU) {
                v0 = gelu_exact(v0); v1 = gelu_exact(v1);
                v2 = gelu_exact(v2); v3 = gelu_exact(v3);
            }
            store2(C, (size_t)m0 * Ndim + n0, v0, v1);
            store2(C, (size_t)(m0 + 8) * Ndim + n0, v2, v3);
        }
    }
}

// ---------------- launch ----------------
extern "C" void kernel_launch(void* const* d_in, const int* in_sizes, int n_in,
                              void* d_out, int out_size) {
    const float* x  = (const float*)d_in[0];
    const float* w1 = (const float*)d_in[1];
    const float* b1 = (const float*)d_in[2];
    const float* w2 = (const float*)d_in[3];
    const float* b2 = (const float*)d_in[4];
    float* out = (float*)d_out;

    __half* w1q = nullptr;  cudaGetSymbolAddress((void**)&w1q, g_w1q);
    __half* w2q = nullptr;  cudaGetSymbolAddress((void**)&w2q, g_w2q);
    __half* xh  = nullptr;  cudaGetSymbolAddress((void**)&xh,  g_x);
    __half* hbuf = nullptr; cudaGetSymbolAddress((void**)&hbuf, g_h);

    const int NW = D_FF * D_MODEL;       // 16,777,216 weights per matrix
    const int NX = M_TOK * D_MODEL;      // 33,554,432 activations

    // raise dynamic smem cap for the GEMM instantiations (host attr, not an alloc)
    cudaFuncSetAttribute(gemm_hmma<true,  __half>,
                         cudaFuncAttributeMaxDynamicSharedMemorySize, SMEM_BYTES);
    cudaFuncSetAttribute(gemm_hmma<false, float>,
                         cudaFuncAttributeMaxDynamicSharedMemorySize, SMEM_BYTES);

    abssum_partial<<<1024, 256>>>(w1, NW, 0);
    abssum_partial<<<1024, 256>>>(w2, NW, 1);
    finalize_scale<<<1, 256>>>(0, 1.0 / NW);
    finalize_scale<<<1, 256>>>(1, 1.0 / NW);

    ternarize4<<<NW / 4 / 256, 256>>>((const float4*)w1, w1q, NW / 4, 0);
    ternarize4<<<NW / 4 / 256, 256>>>((const float4*)w2, w2q, NW / 4, 1);
    convert4<<<NX / 4 / 256, 256>>>((const float4*)x, xh, NX / 4);

    // fc1: [16384,2048] x [8192,2048]^T -> gelu -> h (fp16)
    gemm_hmma<true, __half><<<dim3(D_FF / 128, M_TOK / 128), 256, SMEM_BYTES>>>(
        xh, w1q, b1, hbuf, M_TOK, D_FF, D_MODEL);
    // fc2: [16384,8192] x [2048,8192]^T -> out (fp32)
    gemm_hmma<false, float><<<dim3(D_MODEL / 128, M_TOK / 128), 256, SMEM_BYTES>>>(
        hbuf, w2q, b2, out, M_TOK, D_MODEL, D_FF);
}